// round 5
// baseline (speedup 1.0000x reference)
#include <cuda_runtime.h>
#include <math.h>

#define Hh   256
#define Ww   256
#define HWs  65536
#define Bb   4
#define HIDc 100
#define BHW  (Bb*HWs)      /* 262144  */
#define B2HW (Bb*2*HWs)    /* 524288  */

/* d_out flattened tuple offsets: images(6,B,1,H,W), fields(5,B,2,H,W),
   residuals(6,B,1,H,W), grads(6,B,1,2,H,W) */
#define IMG_OFF 0
#define FLD_OFF (6*BHW)              /* 1572864 */
#define RES_OFF (FLD_OFF + 5*B2HW)   /* 4194304 */
#define GRD_OFF (RES_OFF + 6*BHW)    /* 5767168 */

__device__ float g_hA[Bb*HIDc*HWs];
__device__ float g_hB[Bb*HIDc*HWs];
__device__ float g_def[B2HW];
__device__ float g_ft1[B2HW];
__device__ float g_ft2[B2HW];
__device__ float g_rd[2*6*BHW];
__device__ float g_gauss[51];

typedef unsigned long long u64;

/* ---- packed fp32x2 helpers (Blackwell dual fp32 pipe) ---- */
__device__ __forceinline__ void upk2(u64 v, float &lo, float &hi) {
    asm("mov.b64 {%0,%1}, %2;" : "=f"(lo), "=f"(hi) : "l"(v));
}
__device__ __forceinline__ u64 funnel(u64 a, u64 b) {
    /* returns (hi(a), lo(b)) */
    u64 r;
    asm("{\n\t.reg .b32 al, ah, bl, bh;\n\t"
        "mov.b64 {al, ah}, %1;\n\t"
        "mov.b64 {bl, bh}, %2;\n\t"
        "mov.b64 %0, {ah, bl};\n\t}"
        : "=l"(r) : "l"(a), "l"(b));
    return r;
}
__device__ __forceinline__ void ffma2(u64 &d, u64 a, u64 b) {
    asm("fma.rn.f32x2 %0, %1, %2, %0;" : "+l"(d) : "l"(a), "l"(b));
}

/* ---------------- small kernels ---------------- */

__global__ void k_gauss() {
    if (threadIdx.x == 0) {
        float v[51]; float s = 0.f;
        for (int t = 0; t < 51; t++) {
            float d = ((float)t - 25.0f) / 10.0f;
            v[t] = expf(-0.5f * d * d);
            s += v[t];
        }
        for (int t = 0; t < 51; t++) g_gauss[t] = v[t] / s;
    }
}

__global__ void k_init(const float* __restrict__ src,
                       const float* __restrict__ z0,
                       float* __restrict__ out) {
    int gid = blockIdx.x * blockDim.x + threadIdx.x;
    if (gid >= BHW) return;
    int b = gid / HWs, p = gid % HWs;
    int y = p >> 8, x = p & 255;
    g_def[b*2*HWs + p]       = (float)x;
    g_def[b*2*HWs + HWs + p] = (float)y;
    out[IMG_OFF + gid] = src[gid];
    out[RES_OFF + gid] = z0[p];
}

__global__ void k_grad(const float* __restrict__ img, float* __restrict__ out) {
    int gid = blockIdx.x * blockDim.x + threadIdx.x;
    if (gid >= BHW) return;
    int b = gid / HWs, p = gid % HWs;
    int y = p >> 8, x = p & 255;
    const float* im = img + b*HWs;
    int ym = y > 0 ? y-1 : 0, yp = y < 255 ? y+1 : 255;
    int xm = x > 0 ? x-1 : 0, xp = x < 255 ? x+1 : 255;
    float a00 = im[ym*256+xm], a01 = im[ym*256+x], a02 = im[ym*256+xp];
    float a10 = im[y *256+xm],                     a12 = im[y *256+xp];
    float a20 = im[yp*256+xm], a21 = im[yp*256+x], a22 = im[yp*256+xp];
    float gx = ((a02 - a00) + 2.f*(a12 - a10) + (a22 - a20)) * 0.125f;
    float gy = ((a20 - a00) + 2.f*(a21 - a01) + (a22 - a02)) * 0.125f;
    out[b*2*HWs + p]       = gx;
    out[b*2*HWs + HWs + p] = gy;
}

/* ---------------- conv 3->100, leaky ---------------- */
__global__ __launch_bounds__(256) void k_conv_c3(
    const float* __restrict__ p0, int s0,
    const float* __restrict__ p1, int s1,
    const float* __restrict__ p2, int s2,
    const float* __restrict__ w, float* __restrict__ out)
{
    __shared__ float ws[2700];
    int tx = threadIdx.x, ty = threadIdx.y;
    int tid = ty*32 + tx;
    for (int idx = tid; idx < 2700; idx += 256) ws[idx] = w[idx];

    int b  = blockIdx.z;
    int x0 = blockIdx.x*128 + tx*4;
    int y  = blockIdx.y*8 + ty;
    const float* ch0 = p0 + b*s0;
    const float* ch1 = p1 + b*s1;
    const float* ch2 = p2 + b*s2;

    float v[3][3][6];
#pragma unroll
    for (int ci = 0; ci < 3; ci++) {
        const float* ch = (ci == 0) ? ch0 : (ci == 1 ? ch1 : ch2);
#pragma unroll
        for (int r = 0; r < 3; r++) {
            int yy = y - 1 + r;
            bool yok = (yy >= 0 && yy < 256);
#pragma unroll
            for (int c = 0; c < 6; c++) {
                int xx = x0 - 1 + c;
                v[ci][r][c] = (yok && xx >= 0 && xx < 256) ? ch[yy*256 + xx] : 0.f;
            }
        }
    }
    __syncthreads();

    for (int co = 0; co < 100; co++) {
        float a0 = 0.f, a1 = 0.f, a2 = 0.f, a3 = 0.f;
#pragma unroll
        for (int ci = 0; ci < 3; ci++) {
            const float* wp = &ws[(co*3 + ci)*9];
#pragma unroll
            for (int r = 0; r < 3; r++) {
                float w0 = wp[r*3+0], w1 = wp[r*3+1], w2 = wp[r*3+2];
                a0 += w0*v[ci][r][0] + w1*v[ci][r][1] + w2*v[ci][r][2];
                a1 += w0*v[ci][r][1] + w1*v[ci][r][2] + w2*v[ci][r][3];
                a2 += w0*v[ci][r][2] + w1*v[ci][r][3] + w2*v[ci][r][4];
                a3 += w0*v[ci][r][3] + w1*v[ci][r][4] + w2*v[ci][r][5];
            }
        }
        a0 = a0 >= 0.f ? a0 : 0.01f*a0;
        a1 = a1 >= 0.f ? a1 : 0.01f*a1;
        a2 = a2 >= 0.f ? a2 : 0.01f*a2;
        a3 = a3 >= 0.f ? a3 : 0.01f*a3;
        float4 o = make_float4(a0, a1, a2, a3);
        *(float4*)&out[(b*100 + co)*HWs + y*256 + x0] = o;
    }
}

/* ---------------- conv 100->X (f32x2 packed, 16 px/thread) ---------------- */
/* block (8,16); thread = 16 x-pixels (8 f32x2 pairs) * NCO chans, 1 row.
   Block covers 128x16 pixels. tile: 2 ci planes of 18x132 (gx0 = bx*128-2).
   taps per pair m: left=o[m], center=e[m+1], right=o[m+1].
   EPI 0: leaky -> out (B,100,H,W) at co_base        (NCO=4)
   EPI 1: raw   -> out (B,2,H,W)                     (NCO=2)
   EPI 2: res = prev + acc/5 -> out and out2         (NCO=1) */
template<int NCO, int EPI>
__global__ __launch_bounds__(128) void k_conv100(
    const float* __restrict__ in, const float* __restrict__ wbase,
    float* __restrict__ out, const float* __restrict__ prev,
    float* __restrict__ out2, int cgroups)
{
    __shared__ __align__(16) float tile[2][18][132];
    __shared__ __align__(16) float wdup[NCO*1800];

    int tx = threadIdx.x, ty = threadIdx.y;
    int tid = ty*8 + tx;
    int bz = blockIdx.z;
    int b = bz / cgroups;
    int co_base = (bz % cgroups) * NCO;

    /* weights duplicated into (w,w) pairs for packed broadcast LDS.64 */
    const float* wsl = wbase + co_base*900;
    for (int idx = tid; idx < NCO*900; idx += 128) {
        float w = wsl[idx];
        wdup[2*idx] = w; wdup[2*idx+1] = w;
    }

    int gx0 = blockIdx.x*128 - 2;   /* tile col c <-> global x = gx0 + c */
    int gy0 = blockIdx.y*16 - 1;

    u64 acc[NCO][8];
#pragma unroll
    for (int co = 0; co < NCO; co++)
#pragma unroll
        for (int m = 0; m < 8; m++) acc[co][m] = 0ull;

    const float* inb = in + b*100*HWs;
    float* tf = &tile[0][0][0];

    for (int ci0 = 0; ci0 < 100; ci0 += 2) {
        __syncthreads();
        /* fill two ci planes: 2*18*132 = 4752 floats */
        for (int idx = tid; idx < 4752; idx += 128) {
            int t = idx / 2376, rem = idx - t*2376;
            int r = rem / 132, c = rem - r*132;
            int gy = gy0 + r, gx = gx0 + c;
            float val = 0.f;
            if (gy >= 0 && gy < 256 && gx >= 0 && gx < 256)
                val = inb[(ci0 + t)*HWs + gy*256 + gx];
            tf[idx] = val;
        }
        __syncthreads();

#pragma unroll
        for (int t = 0; t < 2; t++) {
            int ci = ci0 + t;
#pragma unroll
            for (int r = 0; r < 3; r++) {
                const float* rp = &tile[t][ty + r][tx*16];
                u64 e[10], o[9];
#pragma unroll
                for (int k = 0; k < 10; k++) e[k] = *(const u64*)(rp + 2*k);
#pragma unroll
                for (int k = 0; k < 9; k++) o[k] = funnel(e[k], e[k+1]);
#pragma unroll
                for (int co = 0; co < NCO; co++) {
                    const u64* wq = (const u64*)&wdup[(co*900 + ci*9 + r*3)*2];
                    u64 w0 = wq[0], w1 = wq[1], w2 = wq[2];
#pragma unroll
                    for (int m = 0; m < 8; m++) {
                        ffma2(acc[co][m], w0, o[m]);
                        ffma2(acc[co][m], w1, e[m+1]);
                        ffma2(acc[co][m], w2, o[m+1]);
                    }
                }
            }
        }
    }

    int x0 = blockIdx.x*128 + tx*16;
    int y  = blockIdx.y*16 + ty;
    int pbase = y*256 + x0;

    float a[NCO][16];
#pragma unroll
    for (int co = 0; co < NCO; co++)
#pragma unroll
        for (int m = 0; m < 8; m++)
            upk2(acc[co][m], a[co][2*m], a[co][2*m+1]);

    if (EPI == 0) {
#pragma unroll
        for (int co = 0; co < NCO; co++) {
#pragma unroll
            for (int px = 0; px < 16; px++) {
                float v = a[co][px];
                a[co][px] = v >= 0.f ? v : 0.01f*v;
            }
            float* dst = out + (b*100 + co_base + co)*HWs + pbase;
#pragma unroll
            for (int q = 0; q < 4; q++)
                *(float4*)(dst + 4*q) = make_float4(a[co][4*q],a[co][4*q+1],a[co][4*q+2],a[co][4*q+3]);
        }
    } else if (EPI == 1) {
#pragma unroll
        for (int co = 0; co < NCO; co++) {
            float* dst = out + (b*2 + co_base + co)*HWs + pbase;
#pragma unroll
            for (int q = 0; q < 4; q++)
                *(float4*)(dst + 4*q) = make_float4(a[co][4*q],a[co][4*q+1],a[co][4*q+2],a[co][4*q+3]);
        }
    } else {
#pragma unroll
        for (int px = 0; px < 16; px++) {
            float r = prev[b*HWs + pbase + px] + a[0][px] / 5.0f;
            out [b*HWs + pbase + px] = r;
            out2[b*HWs + pbase + px] = r;
        }
    }
}

/* ---------------- blurs ---------------- */

__global__ __launch_bounds__(256) void k_blur_h(const float* __restrict__ in,
                                                float* __restrict__ out) {
    __shared__ float srow[306];
    __shared__ float sg[51];
    int tid = threadIdx.x;
    int rb = blockIdx.x * 256;
    srow[25 + tid] = in[rb + tid];
    if (tid < 25) { srow[tid] = 0.f; srow[281 + tid] = 0.f; }
    if (tid < 51) sg[tid] = g_gauss[tid];
    __syncthreads();
    float acc = 0.f;
#pragma unroll
    for (int k = 0; k < 51; k++) acc += sg[k] * srow[tid + k];
    out[rb + tid] = acc;
}

__global__ __launch_bounds__(256) void k_blur_v(const float* __restrict__ in,
                                                float* __restrict__ fld) {
    __shared__ float sg[51];
    if (threadIdx.x < 51) sg[threadIdx.x] = g_gauss[threadIdx.x];
    __syncthreads();
    int gid = blockIdx.x * 256 + threadIdx.x;
    int x  = gid & 255;
    int y  = (gid >> 8) & 255;
    int ch = gid >> 16;
    const float* col = in + ch*HWs + x;
    float acc = 0.f;
    for (int k = 0; k < 51; k++) {
        int yy = y + k - 25;
        if (yy >= 0 && yy < 256) acc += sg[k] * col[yy*256];
    }
    fld[gid] = acc;
    g_def[gid] -= acc / 5.0f;
}

/* ---------------- deform / compose ---------------- */

__device__ __forceinline__ float bilin(const float* __restrict__ im, float x, float y) {
    float x0f = floorf(x), y0f = floorf(y);
    float wx = x - x0f, wy = y - y0f;
    int x0 = (int)x0f, y0 = (int)y0f;
    float s = 0.f;
#pragma unroll
    for (int dy = 0; dy < 2; dy++) {
        int yi = y0 + dy;
        if (yi < 0 || yi > 255) continue;
        float wyv = dy ? wy : (1.f - wy);
#pragma unroll
        for (int dx = 0; dx < 2; dx++) {
            int xi = x0 + dx;
            if (xi < 0 || xi > 255) continue;
            float wxv = dx ? wx : (1.f - wx);
            s += im[yi*256 + xi] * (wxv * wyv);
        }
    }
    return s;
}

__global__ void k_deform(const float* __restrict__ in, float* __restrict__ out) {
    int gid = blockIdx.x * blockDim.x + threadIdx.x;
    if (gid >= BHW) return;
    int b = gid / HWs, p = gid % HWs;
    float x = g_def[b*2*HWs + p];
    float y = g_def[b*2*HWs + HWs + p];
    out[gid] = bilin(in + b*HWs, x, y);
}

struct Rd5 { const float* p[5]; int n; };

__global__ void k_compose(const float* __restrict__ src,
                          const float* __restrict__ seg,
                          Rd5 rds, float* __restrict__ outimg) {
    int gid = blockIdx.x * blockDim.x + threadIdx.x;
    if (gid >= BHW) return;
    int b = gid / HWs, p = gid % HWs;
    float x = g_def[b*2*HWs + p];
    float y = g_def[b*2*HWs + HWs + p];
    float s = bilin(src + b*HWs, x, y);
    float m = bilin(seg + b*HWs, x, y);
    float acc = rds.p[0][gid];
    for (int j = 1; j < rds.n; j++) acc += rds.p[j][gid];
    outimg[gid] = s + (acc * (float)(0.02*0.02/5.0)) * m;
}

/* ---------------- launch ---------------- */

extern "C" void kernel_launch(void* const* d_in, const int* in_sizes, int n_in,
                              void* d_out, int out_size) {
    const float* src = (const float*)d_in[0];
    const float* seg = (const float*)d_in[1];
    const float* z0  = (const float*)d_in[2];
    const float* zw1 = (const float*)d_in[3];
    const float* zw2 = (const float*)d_in[4];
    const float* zw3 = (const float*)d_in[5];
    const float* vw1 = (const float*)d_in[6];
    const float* vw2 = (const float*)d_in[7];
    const float* vw3 = (const float*)d_in[8];
    float* out = (float*)d_out;

    float *hA, *hB, *defp, *ft1, *ft2, *rd;
    cudaGetSymbolAddress((void**)&hA,  g_hA);
    cudaGetSymbolAddress((void**)&hB,  g_hB);
    cudaGetSymbolAddress((void**)&defp, g_def);
    cudaGetSymbolAddress((void**)&ft1, g_ft1);
    cudaGetSymbolAddress((void**)&ft2, g_ft2);
    cudaGetSymbolAddress((void**)&rd,  g_rd);

    k_gauss<<<1, 32>>>();
    k_init<<<BHW/256, 256>>>(src, z0, out);
    k_grad<<<BHW/256, 256>>>(out + IMG_OFF, out + GRD_OFF);

    dim3 blk3(32, 8), grd3(2, 32, Bb);
    dim3 blkC(8, 16);

    for (int i = 0; i < 5; i++) {
        /* ---- z path: residual update ---- */
        k_conv_c3<<<grd3, blk3>>>(out + RES_OFF + i*BHW, HWs,
                                  out + IMG_OFF + i*BHW, HWs,
                                  out + IMG_OFF,         HWs,
                                  zw1 + i*2700, hA);
        k_conv100<4,0><<<dim3(2,16,Bb*25), blkC>>>(hA, zw2 + i*90000, hB,
                                                   nullptr, nullptr, 25);
        float* rd_new = rd + (((size_t)(i % 2))*6 + (i + 1))*BHW;
        k_conv100<1,2><<<dim3(2,16,Bb), blkC>>>(hB, zw3 + i*900,
                                                out + RES_OFF + (i+1)*BHW,
                                                out + RES_OFF + i*BHW,
                                                rd_new, 1);
        /* ---- re-deform previous residuals with PRE-update deformation ---- */
        for (int j = 1; j <= i; j++) {
            const float* s_ = rd + (((size_t)((i+1) % 2))*6 + j)*BHW;
            float*       d_ = rd + (((size_t)(i % 2))*6 + j)*BHW;
            k_deform<<<BHW/256, 256>>>(s_, d_);
        }
        /* ---- v path: velocity field ---- */
        k_conv_c3<<<grd3, blk3>>>(defp,       2*HWs,
                                  defp + HWs, 2*HWs,
                                  out + IMG_OFF + i*BHW, HWs,
                                  vw1 + i*2700, hA);
        k_conv100<4,0><<<dim3(2,16,Bb*25), blkC>>>(hA, vw2 + i*90000, hB,
                                                   nullptr, nullptr, 25);
        k_conv100<2,1><<<dim3(2,16,Bb), blkC>>>(hB, vw3 + i*1800, ft1,
                                                nullptr, nullptr, 1);
        k_blur_h<<<Bb*2*Hh, 256>>>(ft1, ft2);
        k_blur_v<<<B2HW/256, 256>>>(ft2, out + FLD_OFF + i*B2HW);  /* also updates g_def */

        /* ---- compose new image with POST-update deformation ---- */
        Rd5 rds;
        rds.n = i + 1;
        for (int j = 0; j < 5; j++) {
            int slot = (j <= i) ? (j + 1) : 1;
            rds.p[j] = rd + (((size_t)(i % 2))*6 + slot)*BHW;
        }
        k_compose<<<BHW/256, 256>>>(out + IMG_OFF, seg, rds,
                                    out + IMG_OFF + (i+1)*BHW);
        k_grad<<<BHW/256, 256>>>(out + IMG_OFF + (i+1)*BHW,
                                 out + GRD_OFF + (i+1)*B2HW);
    }
}

// round 6
// speedup vs baseline: 1.2021x; 1.2021x over previous
#include <cuda_runtime.h>
#include <math.h>

#define Hh   256
#define Ww   256
#define HWs  65536
#define Bb   4
#define HIDc 100
#define BHW  (Bb*HWs)      /* 262144  */
#define B2HW (Bb*2*HWs)    /* 524288  */

/* d_out flattened tuple offsets: images(6,B,1,H,W), fields(5,B,2,H,W),
   residuals(6,B,1,H,W), grads(6,B,1,2,H,W) */
#define IMG_OFF 0
#define FLD_OFF (6*BHW)              /* 1572864 */
#define RES_OFF (FLD_OFF + 5*B2HW)   /* 4194304 */
#define GRD_OFF (RES_OFF + 6*BHW)    /* 5767168 */

__device__ float g_hA[Bb*HIDc*HWs];
__device__ float g_hB[Bb*HIDc*HWs];
__device__ float g_def[B2HW];
__device__ float g_ft1[B2HW];
__device__ float g_ft2[B2HW];
__device__ float g_rd[2*6*BHW];
__device__ float g_gauss[51];

typedef unsigned long long u64;

/* ---- packed fp32x2 helpers (Blackwell dual fp32 pipe) ---- */
__device__ __forceinline__ void upk2(u64 v, float &lo, float &hi) {
    asm("mov.b64 {%0,%1}, %2;" : "=f"(lo), "=f"(hi) : "l"(v));
}
__device__ __forceinline__ u64 funnel(u64 a, u64 b) {
    /* returns (hi(a), lo(b)) */
    u64 r;
    asm("{\n\t.reg .b32 al, ah, bl, bh;\n\t"
        "mov.b64 {al, ah}, %1;\n\t"
        "mov.b64 {bl, bh}, %2;\n\t"
        "mov.b64 %0, {ah, bl};\n\t}"
        : "=l"(r) : "l"(a), "l"(b));
    return r;
}
__device__ __forceinline__ void ffma2(u64 &d, u64 a, u64 b) {
    asm("fma.rn.f32x2 %0, %1, %2, %0;" : "+l"(d) : "l"(a), "l"(b));
}

/* ---- cp.async helpers ---- */
__device__ __forceinline__ void cp_async4(float* smem_dst, const float* gptr, bool ok) {
    unsigned sa = (unsigned)__cvta_generic_to_shared(smem_dst);
    int sz = ok ? 4 : 0;
    asm volatile("cp.async.ca.shared.global [%0], [%1], 4, %2;"
                 :: "r"(sa), "l"(gptr), "r"(sz));
}
__device__ __forceinline__ void cp_commit() {
    asm volatile("cp.async.commit_group;");
}
__device__ __forceinline__ void cp_wait1() {
    asm volatile("cp.async.wait_group 1;");
}
__device__ __forceinline__ void cp_wait0() {
    asm volatile("cp.async.wait_group 0;");
}

/* ---------------- small kernels ---------------- */

__global__ void k_gauss() {
    if (threadIdx.x == 0) {
        float v[51]; float s = 0.f;
        for (int t = 0; t < 51; t++) {
            float d = ((float)t - 25.0f) / 10.0f;
            v[t] = expf(-0.5f * d * d);
            s += v[t];
        }
        for (int t = 0; t < 51; t++) g_gauss[t] = v[t] / s;
    }
}

__global__ void k_init(const float* __restrict__ src,
                       const float* __restrict__ z0,
                       float* __restrict__ out) {
    int gid = blockIdx.x * blockDim.x + threadIdx.x;
    if (gid >= BHW) return;
    int b = gid / HWs, p = gid % HWs;
    int y = p >> 8, x = p & 255;
    g_def[b*2*HWs + p]       = (float)x;
    g_def[b*2*HWs + HWs + p] = (float)y;
    out[IMG_OFF + gid] = src[gid];
    out[RES_OFF + gid] = z0[p];
}

__global__ void k_grad(const float* __restrict__ img, float* __restrict__ out) {
    int gid = blockIdx.x * blockDim.x + threadIdx.x;
    if (gid >= BHW) return;
    int b = gid / HWs, p = gid % HWs;
    int y = p >> 8, x = p & 255;
    const float* im = img + b*HWs;
    int ym = y > 0 ? y-1 : 0, yp = y < 255 ? y+1 : 255;
    int xm = x > 0 ? x-1 : 0, xp = x < 255 ? x+1 : 255;
    float a00 = im[ym*256+xm], a01 = im[ym*256+x], a02 = im[ym*256+xp];
    float a10 = im[y *256+xm],                     a12 = im[y *256+xp];
    float a20 = im[yp*256+xm], a21 = im[yp*256+x], a22 = im[yp*256+xp];
    float gx = ((a02 - a00) + 2.f*(a12 - a10) + (a22 - a20)) * 0.125f;
    float gy = ((a20 - a00) + 2.f*(a21 - a01) + (a22 - a02)) * 0.125f;
    out[b*2*HWs + p]       = gx;
    out[b*2*HWs + HWs + p] = gy;
}

/* ---------------- conv 3->100, leaky ---------------- */
__global__ __launch_bounds__(256) void k_conv_c3(
    const float* __restrict__ p0, int s0,
    const float* __restrict__ p1, int s1,
    const float* __restrict__ p2, int s2,
    const float* __restrict__ w, float* __restrict__ out)
{
    __shared__ float ws[2700];
    int tx = threadIdx.x, ty = threadIdx.y;
    int tid = ty*32 + tx;
    for (int idx = tid; idx < 2700; idx += 256) ws[idx] = w[idx];

    int b  = blockIdx.z;
    int x0 = blockIdx.x*128 + tx*4;
    int y  = blockIdx.y*8 + ty;
    const float* ch0 = p0 + b*s0;
    const float* ch1 = p1 + b*s1;
    const float* ch2 = p2 + b*s2;

    float v[3][3][6];
#pragma unroll
    for (int ci = 0; ci < 3; ci++) {
        const float* ch = (ci == 0) ? ch0 : (ci == 1 ? ch1 : ch2);
#pragma unroll
        for (int r = 0; r < 3; r++) {
            int yy = y - 1 + r;
            bool yok = (yy >= 0 && yy < 256);
#pragma unroll
            for (int c = 0; c < 6; c++) {
                int xx = x0 - 1 + c;
                v[ci][r][c] = (yok && xx >= 0 && xx < 256) ? ch[yy*256 + xx] : 0.f;
            }
        }
    }
    __syncthreads();

    for (int co = 0; co < 100; co++) {
        float a0 = 0.f, a1 = 0.f, a2 = 0.f, a3 = 0.f;
#pragma unroll
        for (int ci = 0; ci < 3; ci++) {
            const float* wp = &ws[(co*3 + ci)*9];
#pragma unroll
            for (int r = 0; r < 3; r++) {
                float w0 = wp[r*3+0], w1 = wp[r*3+1], w2 = wp[r*3+2];
                a0 += w0*v[ci][r][0] + w1*v[ci][r][1] + w2*v[ci][r][2];
                a1 += w0*v[ci][r][1] + w1*v[ci][r][2] + w2*v[ci][r][3];
                a2 += w0*v[ci][r][2] + w1*v[ci][r][3] + w2*v[ci][r][4];
                a3 += w0*v[ci][r][3] + w1*v[ci][r][4] + w2*v[ci][r][5];
            }
        }
        a0 = a0 >= 0.f ? a0 : 0.01f*a0;
        a1 = a1 >= 0.f ? a1 : 0.01f*a1;
        a2 = a2 >= 0.f ? a2 : 0.01f*a2;
        a3 = a3 >= 0.f ? a3 : 0.01f*a3;
        float4 o = make_float4(a0, a1, a2, a3);
        *(float4*)&out[(b*100 + co)*HWs + y*256 + x0] = o;
    }
}

/* ---------------- conv 100->X (f32x2 packed, cp.async pipelined) ---------- */
/* block (8,16); thread = 8 x-pixels (4 f32x2 pairs) * NCO chans, 1 row.
   Block covers 64x16 px. Double-buffered: 2 bufs x 2 ci-planes of 18x68.
   EPI 0: leaky -> out (B,100,H,W) at co_base        (NCO=4)
   EPI 1: raw   -> out (B,2,H,W)                     (NCO=2)
   EPI 2: res = prev + acc/5 -> out and out2         (NCO=1) */
#define TROW 68
#define TPLANE (18*TROW)       /* 1224 floats */
#define TBUF  (2*TPLANE)       /* 2448 floats */

template<int NCO, int EPI>
__global__ __launch_bounds__(128) void k_conv100(
    const float* __restrict__ in, const float* __restrict__ wbase,
    float* __restrict__ out, const float* __restrict__ prev,
    float* __restrict__ out2, int cgroups)
{
    __shared__ __align__(16) float tile[2][TBUF];
    __shared__ __align__(16) float wdup[NCO*1800];

    int tx = threadIdx.x, ty = threadIdx.y;
    int tid = ty*8 + tx;
    int bz = blockIdx.z;
    int b = bz / cgroups;
    int co_base = (bz % cgroups) * NCO;

    /* weights duplicated into (w,w) pairs for packed broadcast LDS.64 */
    const float* wsl = wbase + co_base*900;
    for (int idx = tid; idx < NCO*900; idx += 128) {
        float w = wsl[idx];
        wdup[2*idx] = w; wdup[2*idx+1] = w;
    }

    int gx0 = blockIdx.x*64 - 1;
    int gy0 = blockIdx.y*16 - 1;

    u64 acc[NCO][4];
#pragma unroll
    for (int co = 0; co < NCO; co++)
#pragma unroll
        for (int j = 0; j < 4; j++) acc[co][j] = 0ull;

    const float* inb = in + b*100*HWs;

    /* async fill of one 2-plane buffer for channel pair starting at ci0 */
    auto fill = [&](int which, int ci0) {
        float* dst = &tile[which][0];
        const float* srcp = inb + ci0*HWs;
        for (int idx = tid; idx < TBUF; idx += 128) {
            int t = idx / TPLANE, rem = idx - t*TPLANE;
            int r = rem / TROW, c = rem - r*TROW;
            int gy = gy0 + r, gx = gx0 + c;
            bool ok = (gy >= 0) & (gy < 256) & (gx >= 0) & (gx < 256) & (c < 66);
            const float* gp = ok ? (srcp + t*HWs + gy*256 + gx) : srcp;
            cp_async4(dst + idx, gp, ok);
        }
    };

    fill(0, 0);
    cp_commit();

    int cur = 0;
    for (int ci0 = 0; ci0 < 100; ci0 += 2) {
        __syncthreads();               /* everyone done with buf[1-cur] */
        if (ci0 + 2 < 100) {
            fill(1 - cur, ci0 + 2);
            cp_commit();
            cp_wait1();                /* current buffer's group done */
        } else {
            cp_wait0();
        }
        __syncthreads();

#pragma unroll
        for (int t = 0; t < 2; t++) {
            int ci = ci0 + t;
#pragma unroll
            for (int r = 0; r < 3; r++) {
                const float* rp = &tile[cur][t*TPLANE + (ty + r)*TROW + tx*8];
                float4 q0 = *(const float4*)rp;
                float4 q1 = *(const float4*)(rp + 4);
                u64 e[5], o[4];
                e[0] = ((const u64*)&q0)[0]; e[1] = ((const u64*)&q0)[1];
                e[2] = ((const u64*)&q1)[0]; e[3] = ((const u64*)&q1)[1];
                e[4] = *(const u64*)(rp + 8);
#pragma unroll
                for (int k = 0; k < 4; k++) o[k] = funnel(e[k], e[k+1]);
#pragma unroll
                for (int co = 0; co < NCO; co++) {
                    const u64* wq = (const u64*)&wdup[(co*900 + ci*9 + r*3)*2];
                    u64 w0 = wq[0], w1 = wq[1], w2 = wq[2];
#pragma unroll
                    for (int j = 0; j < 4; j++) {
                        ffma2(acc[co][j], w0, e[j]);
                        ffma2(acc[co][j], w1, o[j]);
                        ffma2(acc[co][j], w2, e[j+1]);
                    }
                }
            }
        }
        cur ^= 1;
    }

    int x0 = blockIdx.x*64 + tx*8;
    int y  = blockIdx.y*16 + ty;
    int pbase = y*256 + x0;

    float a[NCO][8];
#pragma unroll
    for (int co = 0; co < NCO; co++)
#pragma unroll
        for (int j = 0; j < 4; j++) upk2(acc[co][j], a[co][2*j], a[co][2*j+1]);

    if (EPI == 0) {
#pragma unroll
        for (int co = 0; co < NCO; co++) {
#pragma unroll
            for (int px = 0; px < 8; px++) {
                float v = a[co][px];
                a[co][px] = v >= 0.f ? v : 0.01f*v;
            }
            float* dst = out + (b*100 + co_base + co)*HWs + pbase;
            *(float4*)dst     = make_float4(a[co][0],a[co][1],a[co][2],a[co][3]);
            *(float4*)(dst+4) = make_float4(a[co][4],a[co][5],a[co][6],a[co][7]);
        }
    } else if (EPI == 1) {
#pragma unroll
        for (int co = 0; co < NCO; co++) {
            float* dst = out + (b*2 + co_base + co)*HWs + pbase;
            *(float4*)dst     = make_float4(a[co][0],a[co][1],a[co][2],a[co][3]);
            *(float4*)(dst+4) = make_float4(a[co][4],a[co][5],a[co][6],a[co][7]);
        }
    } else {
#pragma unroll
        for (int px = 0; px < 8; px++) {
            float r = prev[b*HWs + pbase + px] + a[0][px] / 5.0f;
            out [b*HWs + pbase + px] = r;
            out2[b*HWs + pbase + px] = r;
        }
    }
}

/* ---------------- blurs ---------------- */

__global__ __launch_bounds__(256) void k_blur_h(const float* __restrict__ in,
                                                float* __restrict__ out) {
    __shared__ float srow[306];
    __shared__ float sg[51];
    int tid = threadIdx.x;
    int rb = blockIdx.x * 256;
    srow[25 + tid] = in[rb + tid];
    if (tid < 25) { srow[tid] = 0.f; srow[281 + tid] = 0.f; }
    if (tid < 51) sg[tid] = g_gauss[tid];
    __syncthreads();
    float acc = 0.f;
#pragma unroll
    for (int k = 0; k < 51; k++) acc += sg[k] * srow[tid + k];
    out[rb + tid] = acc;
}

__global__ __launch_bounds__(256) void k_blur_v(const float* __restrict__ in,
                                                float* __restrict__ fld) {
    __shared__ float sg[51];
    if (threadIdx.x < 51) sg[threadIdx.x] = g_gauss[threadIdx.x];
    __syncthreads();
    int gid = blockIdx.x * 256 + threadIdx.x;
    int x  = gid & 255;
    int y  = (gid >> 8) & 255;
    int ch = gid >> 16;
    const float* col = in + ch*HWs + x;
    float acc = 0.f;
    for (int k = 0; k < 51; k++) {
        int yy = y + k - 25;
        if (yy >= 0 && yy < 256) acc += sg[k] * col[yy*256];
    }
    fld[gid] = acc;
    g_def[gid] -= acc / 5.0f;
}

/* ---------------- deform / compose ---------------- */

__device__ __forceinline__ float bilin(const float* __restrict__ im, float x, float y) {
    float x0f = floorf(x), y0f = floorf(y);
    float wx = x - x0f, wy = y - y0f;
    int x0 = (int)x0f, y0 = (int)y0f;
    float s = 0.f;
#pragma unroll
    for (int dy = 0; dy < 2; dy++) {
        int yi = y0 + dy;
        if (yi < 0 || yi > 255) continue;
        float wyv = dy ? wy : (1.f - wy);
#pragma unroll
        for (int dx = 0; dx < 2; dx++) {
            int xi = x0 + dx;
            if (xi < 0 || xi > 255) continue;
            float wxv = dx ? wx : (1.f - wx);
            s += im[yi*256 + xi] * (wxv * wyv);
        }
    }
    return s;
}

__global__ void k_deform(const float* __restrict__ in, float* __restrict__ out) {
    int gid = blockIdx.x * blockDim.x + threadIdx.x;
    if (gid >= BHW) return;
    int b = gid / HWs, p = gid % HWs;
    float x = g_def[b*2*HWs + p];
    float y = g_def[b*2*HWs + HWs + p];
    out[gid] = bilin(in + b*HWs, x, y);
}

struct Rd5 { const float* p[5]; int n; };

__global__ void k_compose(const float* __restrict__ src,
                          const float* __restrict__ seg,
                          Rd5 rds, float* __restrict__ outimg) {
    int gid = blockIdx.x * blockDim.x + threadIdx.x;
    if (gid >= BHW) return;
    int b = gid / HWs, p = gid % HWs;
    float x = g_def[b*2*HWs + p];
    float y = g_def[b*2*HWs + HWs + p];
    float s = bilin(src + b*HWs, x, y);
    float m = bilin(seg + b*HWs, x, y);
    float acc = rds.p[0][gid];
    for (int j = 1; j < rds.n; j++) acc += rds.p[j][gid];
    outimg[gid] = s + (acc * (float)(0.02*0.02/5.0)) * m;
}

/* ---------------- launch ---------------- */

extern "C" void kernel_launch(void* const* d_in, const int* in_sizes, int n_in,
                              void* d_out, int out_size) {
    const float* src = (const float*)d_in[0];
    const float* seg = (const float*)d_in[1];
    const float* z0  = (const float*)d_in[2];
    const float* zw1 = (const float*)d_in[3];
    const float* zw2 = (const float*)d_in[4];
    const float* zw3 = (const float*)d_in[5];
    const float* vw1 = (const float*)d_in[6];
    const float* vw2 = (const float*)d_in[7];
    const float* vw3 = (const float*)d_in[8];
    float* out = (float*)d_out;

    float *hA, *hB, *defp, *ft1, *ft2, *rd;
    cudaGetSymbolAddress((void**)&hA,  g_hA);
    cudaGetSymbolAddress((void**)&hB,  g_hB);
    cudaGetSymbolAddress((void**)&defp, g_def);
    cudaGetSymbolAddress((void**)&ft1, g_ft1);
    cudaGetSymbolAddress((void**)&ft2, g_ft2);
    cudaGetSymbolAddress((void**)&rd,  g_rd);

    k_gauss<<<1, 32>>>();
    k_init<<<BHW/256, 256>>>(src, z0, out);
    k_grad<<<BHW/256, 256>>>(out + IMG_OFF, out + GRD_OFF);

    dim3 blk3(32, 8), grd3(2, 32, Bb);
    dim3 blkC(8, 16);

    for (int i = 0; i < 5; i++) {
        /* ---- z path: residual update ---- */
        k_conv_c3<<<grd3, blk3>>>(out + RES_OFF + i*BHW, HWs,
                                  out + IMG_OFF + i*BHW, HWs,
                                  out + IMG_OFF,         HWs,
                                  zw1 + i*2700, hA);
        k_conv100<4,0><<<dim3(4,16,Bb*25), blkC>>>(hA, zw2 + i*90000, hB,
                                                   nullptr, nullptr, 25);
        float* rd_new = rd + (((size_t)(i % 2))*6 + (i + 1))*BHW;
        k_conv100<1,2><<<dim3(4,16,Bb), blkC>>>(hB, zw3 + i*900,
                                                out + RES_OFF + (i+1)*BHW,
                                                out + RES_OFF + i*BHW,
                                                rd_new, 1);
        /* ---- re-deform previous residuals with PRE-update deformation ---- */
        for (int j = 1; j <= i; j++) {
            const float* s_ = rd + (((size_t)((i+1) % 2))*6 + j)*BHW;
            float*       d_ = rd + (((size_t)(i % 2))*6 + j)*BHW;
            k_deform<<<BHW/256, 256>>>(s_, d_);
        }
        /* ---- v path: velocity field ---- */
        k_conv_c3<<<grd3, blk3>>>(defp,       2*HWs,
                                  defp + HWs, 2*HWs,
                                  out + IMG_OFF + i*BHW, HWs,
                                  vw1 + i*2700, hA);
        k_conv100<4,0><<<dim3(4,16,Bb*25), blkC>>>(hA, vw2 + i*90000, hB,
                                                   nullptr, nullptr, 25);
        k_conv100<2,1><<<dim3(4,16,Bb), blkC>>>(hB, vw3 + i*1800, ft1,
                                                nullptr, nullptr, 1);
        k_blur_h<<<Bb*2*Hh, 256>>>(ft1, ft2);
        k_blur_v<<<B2HW/256, 256>>>(ft2, out + FLD_OFF + i*B2HW);  /* also updates g_def */

        /* ---- compose new image with POST-update deformation ---- */
        Rd5 rds;
        rds.n = i + 1;
        for (int j = 0; j < 5; j++) {
            int slot = (j <= i) ? (j + 1) : 1;
            rds.p[j] = rd + (((size_t)(i % 2))*6 + slot)*BHW;
        }
        k_compose<<<BHW/256, 256>>>(out + IMG_OFF, seg, rds,
                                    out + IMG_OFF + (i+1)*BHW);
        k_grad<<<BHW/256, 256>>>(out + IMG_OFF + (i+1)*BHW,
                                 out + GRD_OFF + (i+1)*B2HW);
    }
}

// round 7
// speedup vs baseline: 1.6692x; 1.3885x over previous
#include <cuda_runtime.h>
#include <math.h>

#define Hh   256
#define Ww   256
#define HWs  65536
#define Bb   4
#define HIDc 100
#define BHW  (Bb*HWs)      /* 262144  */
#define B2HW (Bb*2*HWs)    /* 524288  */

/* d_out flattened tuple offsets: images(6,B,1,H,W), fields(5,B,2,H,W),
   residuals(6,B,1,H,W), grads(6,B,1,2,H,W) */
#define IMG_OFF 0
#define FLD_OFF (6*BHW)              /* 1572864 */
#define RES_OFF (FLD_OFF + 5*B2HW)   /* 4194304 */
#define GRD_OFF (RES_OFF + 6*BHW)    /* 5767168 */

__device__ float g_hA[Bb*HIDc*HWs];
__device__ float g_hB[Bb*HIDc*HWs];
__device__ float g_def[B2HW];
__device__ float g_ft1[B2HW];
__device__ float g_ft2[B2HW];
__device__ float g_rd[2*6*BHW];
__device__ float g_gauss[51];

typedef unsigned long long u64;

/* ---- packed fp32x2 helpers (Blackwell dual fp32 pipe) ---- */
__device__ __forceinline__ void upk2(u64 v, float &lo, float &hi) {
    asm("mov.b64 {%0,%1}, %2;" : "=f"(lo), "=f"(hi) : "l"(v));
}
__device__ __forceinline__ u64 funnel(u64 a, u64 b) {
    /* returns (hi(a), lo(b)) */
    u64 r;
    asm("{\n\t.reg .b32 al, ah, bl, bh;\n\t"
        "mov.b64 {al, ah}, %1;\n\t"
        "mov.b64 {bl, bh}, %2;\n\t"
        "mov.b64 %0, {ah, bl};\n\t}"
        : "=l"(r) : "l"(a), "l"(b));
    return r;
}
__device__ __forceinline__ void ffma2(u64 &d, u64 a, u64 b) {
    asm("fma.rn.f32x2 %0, %1, %2, %0;" : "+l"(d) : "l"(a), "l"(b));
}

/* ---- cp.async helpers ---- */
__device__ __forceinline__ void cp_async16(float* smem_dst, const float* gptr, bool ok) {
    unsigned sa = (unsigned)__cvta_generic_to_shared(smem_dst);
    int sz = ok ? 16 : 0;
    asm volatile("cp.async.cg.shared.global [%0], [%1], 16, %2;"
                 :: "r"(sa), "l"(gptr), "r"(sz));
}
__device__ __forceinline__ void cp_commit() {
    asm volatile("cp.async.commit_group;");
}
__device__ __forceinline__ void cp_wait1() {
    asm volatile("cp.async.wait_group 1;");
}

/* ---------------- small kernels ---------------- */

__global__ void k_gauss() {
    if (threadIdx.x == 0) {
        float v[51]; float s = 0.f;
        for (int t = 0; t < 51; t++) {
            float d = ((float)t - 25.0f) / 10.0f;
            v[t] = expf(-0.5f * d * d);
            s += v[t];
        }
        for (int t = 0; t < 51; t++) g_gauss[t] = v[t] / s;
    }
}

/* fused: deformation init + copy img/res + grad of source */
__global__ void k_init(const float* __restrict__ src,
                       const float* __restrict__ z0,
                       float* __restrict__ out) {
    int gid = blockIdx.x * blockDim.x + threadIdx.x;
    if (gid >= BHW) return;
    int b = gid / HWs, p = gid % HWs;
    int y = p >> 8, x = p & 255;
    g_def[b*2*HWs + p]       = (float)x;
    g_def[b*2*HWs + HWs + p] = (float)y;
    out[IMG_OFF + gid] = src[gid];
    out[RES_OFF + gid] = z0[p];
    const float* im = src + b*HWs;
    int ym = y > 0 ? y-1 : 0, yp = y < 255 ? y+1 : 255;
    int xm = x > 0 ? x-1 : 0, xp = x < 255 ? x+1 : 255;
    float a00 = im[ym*256+xm], a01 = im[ym*256+x], a02 = im[ym*256+xp];
    float a10 = im[y *256+xm],                     a12 = im[y *256+xp];
    float a20 = im[yp*256+xm], a21 = im[yp*256+x], a22 = im[yp*256+xp];
    out[GRD_OFF + b*2*HWs + p]       = ((a02 - a00) + 2.f*(a12 - a10) + (a22 - a20)) * 0.125f;
    out[GRD_OFF + b*2*HWs + HWs + p] = ((a20 - a00) + 2.f*(a21 - a01) + (a22 - a02)) * 0.125f;
}

__global__ void k_grad(const float* __restrict__ img, float* __restrict__ out) {
    int gid = blockIdx.x * blockDim.x + threadIdx.x;
    if (gid >= BHW) return;
    int b = gid / HWs, p = gid % HWs;
    int y = p >> 8, x = p & 255;
    const float* im = img + b*HWs;
    int ym = y > 0 ? y-1 : 0, yp = y < 255 ? y+1 : 255;
    int xm = x > 0 ? x-1 : 0, xp = x < 255 ? x+1 : 255;
    float a00 = im[ym*256+xm], a01 = im[ym*256+x], a02 = im[ym*256+xp];
    float a10 = im[y *256+xm],                     a12 = im[y *256+xp];
    float a20 = im[yp*256+xm], a21 = im[yp*256+x], a22 = im[yp*256+xp];
    float gx = ((a02 - a00) + 2.f*(a12 - a10) + (a22 - a20)) * 0.125f;
    float gy = ((a20 - a00) + 2.f*(a21 - a01) + (a22 - a02)) * 0.125f;
    out[b*2*HWs + p]       = gx;
    out[b*2*HWs + HWs + p] = gy;
}

/* ---------------- conv 3->100, leaky (50 co per block) ---------------- */
__global__ __launch_bounds__(256) void k_conv_c3(
    const float* __restrict__ p0, int s0,
    const float* __restrict__ p1, int s1,
    const float* __restrict__ p2, int s2,
    const float* __restrict__ w, float* __restrict__ out)
{
    __shared__ float ws[1350];
    int tx = threadIdx.x, ty = threadIdx.y;
    int tid = ty*32 + tx;
    int bz = blockIdx.z;
    int b  = bz >> 1;
    int co_base = (bz & 1) * 50;
    for (int idx = tid; idx < 1350; idx += 256) ws[idx] = w[co_base*27 + idx];

    int x0 = blockIdx.x*128 + tx*4;
    int y  = blockIdx.y*8 + ty;
    const float* ch0 = p0 + b*s0;
    const float* ch1 = p1 + b*s1;
    const float* ch2 = p2 + b*s2;

    float v[3][3][6];
#pragma unroll
    for (int ci = 0; ci < 3; ci++) {
        const float* ch = (ci == 0) ? ch0 : (ci == 1 ? ch1 : ch2);
#pragma unroll
        for (int r = 0; r < 3; r++) {
            int yy = y - 1 + r;
            bool yok = (yy >= 0 && yy < 256);
#pragma unroll
            for (int c = 0; c < 6; c++) {
                int xx = x0 - 1 + c;
                v[ci][r][c] = (yok && xx >= 0 && xx < 256) ? ch[yy*256 + xx] : 0.f;
            }
        }
    }
    __syncthreads();

    for (int co = 0; co < 50; co++) {
        float a0 = 0.f, a1 = 0.f, a2 = 0.f, a3 = 0.f;
#pragma unroll
        for (int ci = 0; ci < 3; ci++) {
            const float* wp = &ws[(co*3 + ci)*9];
#pragma unroll
            for (int r = 0; r < 3; r++) {
                float w0 = wp[r*3+0], w1 = wp[r*3+1], w2 = wp[r*3+2];
                a0 += w0*v[ci][r][0] + w1*v[ci][r][1] + w2*v[ci][r][2];
                a1 += w0*v[ci][r][1] + w1*v[ci][r][2] + w2*v[ci][r][3];
                a2 += w0*v[ci][r][2] + w1*v[ci][r][3] + w2*v[ci][r][4];
                a3 += w0*v[ci][r][3] + w1*v[ci][r][4] + w2*v[ci][r][5];
            }
        }
        a0 = a0 >= 0.f ? a0 : 0.01f*a0;
        a1 = a1 >= 0.f ? a1 : 0.01f*a1;
        a2 = a2 >= 0.f ? a2 : 0.01f*a2;
        a3 = a3 >= 0.f ? a3 : 0.01f*a3;
        float4 o = make_float4(a0, a1, a2, a3);
        *(float4*)&out[(b*100 + co_base + co)*HWs + y*256 + x0] = o;
    }
}

/* ---------------- conv 100->X (f32x2, vec16 fill, 3-stage pipeline) ------- */
/* block (8,16); thread = 8 x-pixels (4 f32x2 pairs) * NCO chans, 1 row.
   Block covers 64x16 px. 3 bufs x 1 ci-plane of 18x72 floats; tile col c
   maps to global x = bx*64 - 4 + c (16B-aligned global chunks).
   EPI 0: leaky -> out (B,100,H,W) at co_base        (NCO=4)
   EPI 1: raw   -> out (B,2,H,W)                     (NCO=2)
   EPI 2: res = prev + acc/5 -> out and out2         (NCO=1) */
#define TROW 72
#define TPLANE (18*TROW)       /* 1296 floats */

template<int NCO, int EPI>
__global__ __launch_bounds__(128) void k_conv100(
    const float* __restrict__ in, const float* __restrict__ wbase,
    float* __restrict__ out, const float* __restrict__ prev,
    float* __restrict__ out2, int cgroups)
{
    __shared__ __align__(16) float tile[3][TPLANE];
    __shared__ __align__(16) float wdup[NCO*1800];

    int tx = threadIdx.x, ty = threadIdx.y;
    int tid = ty*8 + tx;
    int bz = blockIdx.z;
    int b = bz / cgroups;
    int co_base = (bz % cgroups) * NCO;

    /* weights duplicated into (w,w) pairs for packed broadcast LDS.64 */
    const float* wsl = wbase + co_base*900;
    for (int idx = tid; idx < NCO*900; idx += 128) {
        float w = wsl[idx];
        wdup[2*idx] = w; wdup[2*idx+1] = w;
    }

    int gbx = blockIdx.x*64 - 4;   /* tile col c <-> global x = gbx + c */
    int gy0 = blockIdx.y*16 - 1;

    u64 acc[NCO][4];
#pragma unroll
    for (int co = 0; co < NCO; co++)
#pragma unroll
        for (int j = 0; j < 4; j++) acc[co][j] = 0ull;

    const float* inb = in + b*100*HWs;

    /* async vec16 fill of one ci plane: 18 rows x 18 chunks */
    auto fill = [&](int slot, int ci) {
        float* dst = &tile[slot][0];
        const float* srcp = inb + ci*HWs;
#pragma unroll
        for (int u = 0; u < 3; u++) {
            int idx = tid + u*128;
            if (idx < 324) {
                int r = idx / 18, c = idx - r*18;
                int gy = gy0 + r;
                int gxs = gbx + 4*c;
                bool ok = (gy >= 0) & (gy < 256) & (gxs >= 0) & (gxs <= 252);
                const float* gp = ok ? (srcp + gy*256 + gxs) : srcp;
                cp_async16(dst + r*TROW + 4*c, gp, ok);
            }
        }
    };

    fill(0, 0); cp_commit();
    fill(1, 1); cp_commit();

    int slot = 0;
    for (int ci = 0; ci < 100; ci++) {
        cp_wait1();
        __syncthreads();

#pragma unroll
        for (int r = 0; r < 3; r++) {
            const float* rp = &tile[slot][(ty + r)*TROW + tx*8];
            u64 eL = *(const u64*)(rp + 2);
            float4 q0 = *(const float4*)(rp + 4);
            float4 q1 = *(const float4*)(rp + 8);
            u64 e4 = *(const u64*)(rp + 12);
            u64 e0 = ((const u64*)&q0)[0], e1 = ((const u64*)&q0)[1];
            u64 e2 = ((const u64*)&q1)[0], e3 = ((const u64*)&q1)[1];
            u64 o0 = funnel(eL, e0);
            u64 o1 = funnel(e0, e1);
            u64 o2 = funnel(e1, e2);
            u64 o3 = funnel(e2, e3);
            u64 o4 = funnel(e3, e4);
#pragma unroll
            for (int co = 0; co < NCO; co++) {
                const u64* wq = (const u64*)&wdup[(co*900 + ci*9 + r*3)*2];
                u64 w0 = wq[0], w1 = wq[1], w2 = wq[2];
                /* tap-outer: acc reuse distance = 4 instructions */
                ffma2(acc[co][0], w0, o0);
                ffma2(acc[co][1], w0, o1);
                ffma2(acc[co][2], w0, o2);
                ffma2(acc[co][3], w0, o3);
                ffma2(acc[co][0], w1, e0);
                ffma2(acc[co][1], w1, e1);
                ffma2(acc[co][2], w1, e2);
                ffma2(acc[co][3], w1, e3);
                ffma2(acc[co][0], w2, o1);
                ffma2(acc[co][1], w2, o2);
                ffma2(acc[co][2], w2, o3);
                ffma2(acc[co][3], w2, o4);
            }
        }

        if (ci + 2 < 100) fill(slot == 2 ? 1 : (slot == 1 ? 0 : 2), ci + 2);
        /* slot of ci+2 = (ci+2)%3; since slot = ci%3, (ci+2)%3 = (slot+2)%3 */
        cp_commit();
        slot = (slot == 2) ? 0 : slot + 1;
    }

    int x0 = blockIdx.x*64 + tx*8;
    int y  = blockIdx.y*16 + ty;
    int pbase = y*256 + x0;

    float a[NCO][8];
#pragma unroll
    for (int co = 0; co < NCO; co++)
#pragma unroll
        for (int j = 0; j < 4; j++) upk2(acc[co][j], a[co][2*j], a[co][2*j+1]);

    if (EPI == 0) {
#pragma unroll
        for (int co = 0; co < NCO; co++) {
#pragma unroll
            for (int px = 0; px < 8; px++) {
                float v = a[co][px];
                a[co][px] = v >= 0.f ? v : 0.01f*v;
            }
            float* dst = out + (b*100 + co_base + co)*HWs + pbase;
            *(float4*)dst     = make_float4(a[co][0],a[co][1],a[co][2],a[co][3]);
            *(float4*)(dst+4) = make_float4(a[co][4],a[co][5],a[co][6],a[co][7]);
        }
    } else if (EPI == 1) {
#pragma unroll
        for (int co = 0; co < NCO; co++) {
            float* dst = out + (b*2 + co_base + co)*HWs + pbase;
            *(float4*)dst     = make_float4(a[co][0],a[co][1],a[co][2],a[co][3]);
            *(float4*)(dst+4) = make_float4(a[co][4],a[co][5],a[co][6],a[co][7]);
        }
    } else {
#pragma unroll
        for (int px = 0; px < 8; px++) {
            float r = prev[b*HWs + pbase + px] + a[0][px] / 5.0f;
            out [b*HWs + pbase + px] = r;
            out2[b*HWs + pbase + px] = r;
        }
    }
}

/* ---------------- blurs ---------------- */

__global__ __launch_bounds__(256) void k_blur_h(const float* __restrict__ in,
                                                float* __restrict__ out) {
    __shared__ float srow[306];
    __shared__ float sg[51];
    int tid = threadIdx.x;
    int rb = blockIdx.x * 256;
    srow[25 + tid] = in[rb + tid];
    if (tid < 25) { srow[tid] = 0.f; srow[281 + tid] = 0.f; }
    if (tid < 51) sg[tid] = g_gauss[tid];
    __syncthreads();
    float acc = 0.f;
#pragma unroll
    for (int k = 0; k < 51; k++) acc += sg[k] * srow[tid + k];
    out[rb + tid] = acc;
}

__global__ __launch_bounds__(256) void k_blur_v(const float* __restrict__ in,
                                                float* __restrict__ fld) {
    __shared__ float sg[51];
    if (threadIdx.x < 51) sg[threadIdx.x] = g_gauss[threadIdx.x];
    __syncthreads();
    int gid = blockIdx.x * 256 + threadIdx.x;
    int x  = gid & 255;
    int y  = (gid >> 8) & 255;
    int ch = gid >> 16;
    const float* col = in + ch*HWs + x;
    float acc = 0.f;
    for (int k = 0; k < 51; k++) {
        int yy = y + k - 25;
        if (yy >= 0 && yy < 256) acc += sg[k] * col[yy*256];
    }
    fld[gid] = acc;
    g_def[gid] -= acc / 5.0f;
}

/* ---------------- deform / compose ---------------- */

__device__ __forceinline__ float bilin(const float* __restrict__ im, float x, float y) {
    float x0f = floorf(x), y0f = floorf(y);
    float wx = x - x0f, wy = y - y0f;
    int x0 = (int)x0f, y0 = (int)y0f;
    float s = 0.f;
#pragma unroll
    for (int dy = 0; dy < 2; dy++) {
        int yi = y0 + dy;
        if (yi < 0 || yi > 255) continue;
        float wyv = dy ? wy : (1.f - wy);
#pragma unroll
        for (int dx = 0; dx < 2; dx++) {
            int xi = x0 + dx;
            if (xi < 0 || xi > 255) continue;
            float wxv = dx ? wx : (1.f - wx);
            s += im[yi*256 + xi] * (wxv * wyv);
        }
    }
    return s;
}

__global__ void k_deform(const float* __restrict__ in, float* __restrict__ out) {
    int gid = blockIdx.x * blockDim.x + threadIdx.x;
    if (gid >= BHW) return;
    int b = gid / HWs, p = gid % HWs;
    float x = g_def[b*2*HWs + p];
    float y = g_def[b*2*HWs + HWs + p];
    out[gid] = bilin(in + b*HWs, x, y);
}

struct Rd5 { const float* p[5]; int n; };

__global__ void k_compose(const float* __restrict__ src,
                          const float* __restrict__ seg,
                          Rd5 rds, float* __restrict__ outimg) {
    int gid = blockIdx.x * blockDim.x + threadIdx.x;
    if (gid >= BHW) return;
    int b = gid / HWs, p = gid % HWs;
    float x = g_def[b*2*HWs + p];
    float y = g_def[b*2*HWs + HWs + p];
    float s = bilin(src + b*HWs, x, y);
    float m = bilin(seg + b*HWs, x, y);
    float acc = rds.p[0][gid];
    for (int j = 1; j < rds.n; j++) acc += rds.p[j][gid];
    outimg[gid] = s + (acc * (float)(0.02*0.02/5.0)) * m;
}

/* ---------------- launch ---------------- */

extern "C" void kernel_launch(void* const* d_in, const int* in_sizes, int n_in,
                              void* d_out, int out_size) {
    const float* src = (const float*)d_in[0];
    const float* seg = (const float*)d_in[1];
    const float* z0  = (const float*)d_in[2];
    const float* zw1 = (const float*)d_in[3];
    const float* zw2 = (const float*)d_in[4];
    const float* zw3 = (const float*)d_in[5];
    const float* vw1 = (const float*)d_in[6];
    const float* vw2 = (const float*)d_in[7];
    const float* vw3 = (const float*)d_in[8];
    float* out = (float*)d_out;

    float *hA, *hB, *defp, *ft1, *ft2, *rd;
    cudaGetSymbolAddress((void**)&hA,  g_hA);
    cudaGetSymbolAddress((void**)&hB,  g_hB);
    cudaGetSymbolAddress((void**)&defp, g_def);
    cudaGetSymbolAddress((void**)&ft1, g_ft1);
    cudaGetSymbolAddress((void**)&ft2, g_ft2);
    cudaGetSymbolAddress((void**)&rd,  g_rd);

    k_gauss<<<1, 32>>>();
    k_init<<<BHW/256, 256>>>(src, z0, out);

    dim3 blk3(32, 8), grd3(2, 32, Bb*2);
    dim3 blkC(8, 16);

    for (int i = 0; i < 5; i++) {
        /* ---- z path: residual update ---- */
        k_conv_c3<<<grd3, blk3>>>(out + RES_OFF + i*BHW, HWs,
                                  out + IMG_OFF + i*BHW, HWs,
                                  out + IMG_OFF,         HWs,
                                  zw1 + i*2700, hA);
        k_conv100<4,0><<<dim3(4,16,Bb*25), blkC>>>(hA, zw2 + i*90000, hB,
                                                   nullptr, nullptr, 25);
        float* rd_new = rd + (((size_t)(i % 2))*6 + (i + 1))*BHW;
        k_conv100<1,2><<<dim3(4,16,Bb), blkC>>>(hB, zw3 + i*900,
                                                out + RES_OFF + (i+1)*BHW,
                                                out + RES_OFF + i*BHW,
                                                rd_new, 1);
        /* ---- re-deform previous residuals with PRE-update deformation ---- */
        for (int j = 1; j <= i; j++) {
            const float* s_ = rd + (((size_t)((i+1) % 2))*6 + j)*BHW;
            float*       d_ = rd + (((size_t)(i % 2))*6 + j)*BHW;
            k_deform<<<BHW/256, 256>>>(s_, d_);
        }
        /* ---- v path: velocity field ---- */
        k_conv_c3<<<grd3, blk3>>>(defp,       2*HWs,
                                  defp + HWs, 2*HWs,
                                  out + IMG_OFF + i*BHW, HWs,
                                  vw1 + i*2700, hA);
        k_conv100<4,0><<<dim3(4,16,Bb*25), blkC>>>(hA, vw2 + i*90000, hB,
                                                   nullptr, nullptr, 25);
        k_conv100<2,1><<<dim3(4,16,Bb), blkC>>>(hB, vw3 + i*1800, ft1,
                                                nullptr, nullptr, 1);
        k_blur_h<<<Bb*2*Hh, 256>>>(ft1, ft2);
        k_blur_v<<<B2HW/256, 256>>>(ft2, out + FLD_OFF + i*B2HW);  /* also updates g_def */

        /* ---- compose new image with POST-update deformation ---- */
        Rd5 rds;
        rds.n = i + 1;
        for (int j = 0; j < 5; j++) {
            int slot = (j <= i) ? (j + 1) : 1;
            rds.p[j] = rd + (((size_t)(i % 2))*6 + slot)*BHW;
        }
        k_compose<<<BHW/256, 256>>>(out + IMG_OFF, seg, rds,
                                    out + IMG_OFF + (i+1)*BHW);
        k_grad<<<BHW/256, 256>>>(out + IMG_OFF + (i+1)*BHW,
                                 out + GRD_OFF + (i+1)*B2HW);
    }
}